// round 1
// baseline (speedup 1.0000x reference)
#include <cuda_runtime.h>

// loss = 2*0.5 * dot(colsum(a), colsum(b)),  a,b: [16384, 512] fp32, out: scalar fp32

#define ROWS 16384
#define COLS 512
#define NBLK 256   // colsum grid

__device__ float g_sa[COLS];
__device__ float g_sb[COLS];

__global__ void zero_kernel() {
    int t = threadIdx.x;           // 512 threads
    g_sa[t] = 0.0f;
    g_sb[t] = 0.0f;
}

__global__ __launch_bounds__(COLS) void colsum_kernel(const float* __restrict__ a,
                                                      const float* __restrict__ b) {
    const int c = threadIdx.x;                 // column 0..511
    const int rows_per = ROWS / NBLK;          // 64
    const int r0 = blockIdx.x * rows_per;
    const int r1 = r0 + rows_per;

    float sa = 0.0f, sb = 0.0f;
#pragma unroll 8
    for (int r = r0; r < r1; ++r) {
        sa += a[(size_t)r * COLS + c];
        sb += b[(size_t)r * COLS + c];
    }
    atomicAdd(&g_sa[c], sa);
    atomicAdd(&g_sb[c], sb);
}

__global__ void dot_kernel(float* __restrict__ out) {
    const int t = threadIdx.x;                 // 512 threads
    float v = g_sa[t] * g_sb[t];

    __shared__ float red[16];
#pragma unroll
    for (int o = 16; o > 0; o >>= 1)
        v += __shfl_xor_sync(0xffffffffu, v, o);
    if ((t & 31) == 0) red[t >> 5] = v;
    __syncthreads();
    if (t < 16) {
        float w = red[t];
#pragma unroll
        for (int o = 8; o > 0; o >>= 1)
            w += __shfl_xor_sync(0xffffu, w, o);
        if (t == 0) out[0] = 1.0f * w;   // 2 * LAMBD = 1.0
    }
}

extern "C" void kernel_launch(void* const* d_in, const int* in_sizes, int n_in,
                              void* d_out, int out_size) {
    const float* a = (const float*)d_in[0];
    const float* b = (const float*)d_in[1];
    float* out = (float*)d_out;

    zero_kernel<<<1, COLS>>>();
    colsum_kernel<<<NBLK, COLS>>>(a, b);
    dot_kernel<<<1, COLS>>>(out);
}

// round 2
// speedup vs baseline: 1.1278x; 1.1278x over previous
#include <cuda_runtime.h>

// loss = 2*0.5 * dot(colsum(a), colsum(b)),  a,b: [16384, 512] fp32, out: scalar fp32
// Single fused kernel: partial colsums -> global atomics -> last-block dot + state reset.

#define ROWS 16384
#define COLS 512
#define NBLK 256            // all co-resident on 148 SMs (512 thr/CTA)
#define RPB  (ROWS / NBLK)  // 64 rows per block

__device__ float g_sa[COLS];          // zero-init at module load; re-zeroed each call
__device__ float g_sb[COLS];
__device__ unsigned int g_ticket;     // ditto

__global__ __launch_bounds__(COLS) void fused_kernel(const float* __restrict__ a,
                                                     const float* __restrict__ b,
                                                     float* __restrict__ out) {
    const int c  = threadIdx.x;              // column 0..511 (coalesced across warp)
    const int r0 = blockIdx.x * RPB;

    float sa = 0.0f, sb = 0.0f;
#pragma unroll 8
    for (int r = r0; r < r0 + RPB; ++r) {
        sa += a[(size_t)r * COLS + c];
        sb += b[(size_t)r * COLS + c];
    }
    atomicAdd(&g_sa[c], sa);
    atomicAdd(&g_sb[c], sb);

    // ---- last-block-done ticket ----
    __threadfence();                         // make atomics visible device-wide
    __shared__ bool is_last;
    if (c == 0) {
        unsigned int t = atomicAdd(&g_ticket, 1u);
        is_last = (t == (unsigned)(gridDim.x - 1));
    }
    __syncthreads();
    if (!is_last) return;

    __threadfence();                         // acquire side

    // read colsums via L2 (bypass L1), then reset scratch for the next replay
    float va = __ldcg(&g_sa[c]);
    float vb = __ldcg(&g_sb[c]);
    g_sa[c] = 0.0f;
    g_sb[c] = 0.0f;

    float v = va * vb;
    __shared__ float red[16];
#pragma unroll
    for (int o = 16; o > 0; o >>= 1)
        v += __shfl_xor_sync(0xffffffffu, v, o);
    if ((c & 31) == 0) red[c >> 5] = v;
    __syncthreads();
    if (c < 16) {
        float w = red[c];
#pragma unroll
        for (int o = 8; o > 0; o >>= 1)
            w += __shfl_xor_sync(0xffffu, w, o);
        if (c == 0) {
            out[0] = w;                      // 2 * LAMBD = 1.0
            g_ticket = 0u;                   // reset for next replay
        }
    }
}

extern "C" void kernel_launch(void* const* d_in, const int* in_sizes, int n_in,
                              void* d_out, int out_size) {
    const float* a = (const float*)d_in[0];
    const float* b = (const float*)d_in[1];
    float* out = (float*)d_out;

    fused_kernel<<<NBLK, COLS>>>(a, b, out);
}